// round 16
// baseline (speedup 1.0000x reference)
#include <cuda_runtime.h>
#include <math.h>
#include <stdint.h>

#define DD 64
#define KK 512
#define WST 68               // W row stride in floats: conflict-free frag loads
#define ROWS_PER_CTA 256
#define NTHREADS 256
#define NT (KK / 8)
#define TIE_TAU 3e-5f

typedef unsigned long long u64;
typedef uint32_t u32;

// SMEM words: W exact [512][68] + w2 + w2em + ps scratch (4 mma warps)
#define SM_W    0
#define SM_W2   (KK * WST)
#define SM_W2EM (SM_W2 + KK)
#define SM_PS   (SM_W2EM + KK)
#define SMEM_WORDS (SM_PS + 4 * 144)
#define SMEM_MAIN (SMEM_WORDS * 4)

__device__ __forceinline__ u64 pk2(float a, float b) {
    u64 r; asm("mov.b64 %0,{%1,%2};" : "=l"(r) : "f"(a), "f"(b)); return r;
}
__device__ __forceinline__ void upk2(u64 v, float& a, float& b) {
    asm("mov.b64 {%0,%1},%2;" : "=f"(a), "=f"(b) : "l"(v));
}
__device__ __forceinline__ u64 fma2(u64 a, u64 b, u64 c) {
    u64 d; asm("fma.rn.f32x2 %0,%1,%2,%3;" : "=l"(d) : "l"(a), "l"(b), "l"(c)); return d;
}
__device__ __forceinline__ u64 add2(u64 a, u64 b) {
    u64 d; asm("add.rn.f32x2 %0,%1,%2;" : "=l"(d) : "l"(a), "l"(b)); return d;
}
__device__ __forceinline__ u32 f2tf(float x) {
    u32 r; asm("cvt.rna.tf32.f32 %0,%1;" : "=r"(r) : "f"(x)); return r;
}
__device__ __forceinline__ void mma8(float& c0, float& c1, float& c2, float& c3,
                                     u32 a0, u32 a1, u32 a2, u32 a3, u32 b0, u32 b1) {
    asm volatile(
        "mma.sync.aligned.m16n8k8.row.col.f32.tf32.tf32.f32 "
        "{%0,%1,%2,%3},{%4,%5,%6,%7},{%8,%9},{%0,%1,%2,%3};"
        : "+f"(c0), "+f"(c1), "+f"(c2), "+f"(c3)
        : "r"(a0), "r"(a1), "r"(a2), "r"(a3), "r"(b0), "r"(b1));
}

// Reference-style squared-norm (cold path, R6-validated).
__device__ __forceinline__ float ref_norm2(const float* __restrict__ r) {
    float a[32];
    #pragma unroll
    for (int j = 0; j < 32; j++)
        a[j] = __fadd_rn(__fmul_rn(r[j], r[j]), __fmul_rn(r[j + 32], r[j + 32]));
    #pragma unroll
    for (int j = 0; j < 16; j++) a[j] = __fadd_rn(a[j], a[j + 16]);
    #pragma unroll
    for (int j = 0; j < 8; j++)  a[j] = __fadd_rn(a[j], a[j + 8]);
    #pragma unroll
    for (int j = 0; j < 4; j++)  a[j] = __fadd_rn(a[j], a[j + 4]);
    a[0] = __fadd_rn(a[0], a[2]); a[1] = __fadd_rn(a[1], a[3]);
    return __fadd_rn(a[0], a[1]);
}
__device__ __forceinline__ float fast_negsqrt(float d2) {
    float c = fmaxf(d2, 1e-30f);
    return -(c * rsqrtf(c));
}

// Cold path (rare, R6-validated): bit-faithful reference emulation from GMEM.
__device__ __noinline__ int cold_resolve(const float* __restrict__ xr,
                                         const float* __restrict__ wg,
                                         const float* __restrict__ w2em) {
    float xf[DD];
    #pragma unroll
    for (int d = 0; d < DD; d++) xf[d] = xr[d];
    float x2em = ref_norm2(xf);
    float distbuf[KK];
    float m = -3.4e38f;
    #pragma unroll 1
    for (int k = 0; k < KK; k++) {
        const float* r = wg + k * DD;
        float acc = 0.f;
        #pragma unroll
        for (int d = 0; d < DD; d++) acc = __fmaf_rn(xf[d], r[d], acc);
        float d2 = __fsub_rn(__fadd_rn(x2em, w2em[k]), __fmul_rn(2.f, acc));
        if (d2 < 0.f) d2 = 0.f;
        float dist = -__fsqrt_rn(d2);
        distbuf[k] = dist;
        m = fmaxf(m, dist);
    }
    float ssum = 0.f;
    #pragma unroll 1
    for (int k = 0; k < KK; k++)
        ssum = __fadd_rn(ssum, (float)exp((double)__fsub_rn(distbuf[k], m)));
    float bestv = -1.f;
    int bk = 0;
    #pragma unroll 1
    for (int k = 0; k < KK; k++) {
        float e = (float)exp((double)__fsub_rn(distbuf[k], m));
        float v = __fdiv_rn(e, ssum);
        if (v > bestv) { bestv = v; bk = k; }
    }
    return bk;
}

__global__ __launch_bounds__(NTHREADS, 1)
void sq_main(const float* __restrict__ x, const float* __restrict__ w,
             float* __restrict__ outq, float* __restrict__ outidx, int N) {
    extern __shared__ float sm[];
    float* wsh  = sm + SM_W;
    float* w2sh = sm + SM_W2;
    float* w2em = sm + SM_W2EM;

    int tid = threadIdx.x, wid = tid >> 5, lane = tid & 31;
    int base = blockIdx.x * ROWS_PER_CTA;

    // Stage exact W -> stride-68 SMEM
    for (int i = tid; i < KK * DD / 4; i += NTHREADS) {
        float4 v = ((const float4*)w)[i];
        int k = i >> 4, c = (i & 15) * 4;
        float* dst = wsh + k * WST + c;
        dst[0] = v.x; dst[1] = v.y; dst[2] = v.z; dst[3] = v.w;
    }
    __syncthreads();
    for (int k = tid; k < KK; k += NTHREADS) {
        const float* r = wsh + k * WST;
        float s = 0.f;
        float rl[DD];
        #pragma unroll
        for (int d = 0; d < DD; d++) { rl[d] = r[d]; s += rl[d] * rl[d]; }
        w2sh[k] = s;
        w2em[k] = ref_norm2(rl);
    }
    __syncthreads();

    if (wid < 4) {
        // ───── scalar path: warps 0-3, thread-per-row, rows [base, base+128) ─────
        int row = base + tid;           // tid in [0,128)
        if (row < N) {
            const float4* xr = (const float4*)(x + (size_t)row * DD);
            u64 xp[32];
            float x2 = 0.f;
            #pragma unroll
            for (int i = 0; i < 16; i++) {
                float4 v = xr[i];
                xp[2 * i]     = pk2(v.x, v.y);
                xp[2 * i + 1] = pk2(v.z, v.w);
                x2 += v.x * v.x + v.y * v.y + v.z * v.z + v.w * v.w;
            }
            u64 accp[32];
            #pragma unroll
            for (int i = 0; i < 32; i++) accp[i] = 0ull;

            float s = 0.f, d1 = -3.4e38f, d2t = -3.4e38f;
            int bk = 0;
            #pragma unroll 1
            for (int k = 0; k < KK; k++) {
                const u64* w0 = (const u64*)(wsh + k * WST);
                u64 a0 = 0ull, a1 = 0ull, a2 = 0ull, a3 = 0ull;
                #pragma unroll
                for (int i = 0; i < 32; i += 4) {
                    a0 = fma2(xp[i],     w0[i],     a0);
                    a1 = fma2(xp[i + 1], w0[i + 1], a1);
                    a2 = fma2(xp[i + 2], w0[i + 2], a2);
                    a3 = fma2(xp[i + 3], w0[i + 3], a3);
                }
                u64 t = add2(add2(a0, a1), add2(a2, a3));
                float tl, th; upk2(t, tl, th);
                float dot = tl + th;

                float dd = fmaxf(__fsub_rn(__fadd_rn(x2, w2sh[k]), 2.f * dot), 0.f);
                float dist = fast_negsqrt(dd);
                float e = __expf(dist);       // dist in [-13,0]: shift-0 softmax safe
                s += e;
                if (dist > d1) { d2t = d1; d1 = dist; bk = k; }
                else if (dist > d2t) { d2t = dist; }

                u64 ee = pk2(e, e);
                #pragma unroll
                for (int i = 0; i < 32; i++) accp[i] = fma2(ee, w0[i], accp[i]);
            }
            float inv = 1.f / s;
            float4* qo = (float4*)(outq + (size_t)row * DD);
            #pragma unroll
            for (int i = 0; i < 16; i++) {
                float a, b, c, d;
                upk2(accp[2 * i], a, b);
                upk2(accp[2 * i + 1], c, d);
                float4 v; v.x = a * inv; v.y = b * inv; v.z = c * inv; v.w = d * inv;
                qo[i] = v;
            }
            if (outidx) {
                int b = bk;
                if (d1 - d2t < TIE_TAU) b = cold_resolve(x + (size_t)row * DD, w, w2em);
                outidx[row] = (float)b;
            }
        }
    } else {
        // ───── MMA path: warps 4-7, two 16-row tiles each, rows [base+128, base+256) ─────
        int mwid = wid - 4;
        int g = lane >> 2, t = lane & 3;
        float* ps = sm + SM_PS + mwid * 144;

        #pragma unroll 1
        for (int tile = 0; tile < 2; tile++) {
            int row0 = base + 128 + tile * 64 + mwid * 16 + g;
            int row1 = row0 + 8;
            bool v0 = row0 < N, v1 = row1 < N;
            const float* xr0 = x + (size_t)(v0 ? row0 : 0) * DD;
            const float* xr1 = x + (size_t)(v1 ? row1 : 0) * DD;

            u32 Ah[8][4], Al[8][4];
            float x2r0 = 0.f, x2r1 = 0.f;
            #pragma unroll
            for (int kt = 0; kt < 8; kt++) {
                float a0 = v0 ? xr0[kt * 8 + t]     : 0.f;
                float a1 = v1 ? xr1[kt * 8 + t]     : 0.f;
                float a2 = v0 ? xr0[kt * 8 + t + 4] : 0.f;
                float a3 = v1 ? xr1[kt * 8 + t + 4] : 0.f;
                x2r0 = fmaf(a0, a0, fmaf(a2, a2, x2r0));
                x2r1 = fmaf(a1, a1, fmaf(a3, a3, x2r1));
                Ah[kt][0] = f2tf(a0); Al[kt][0] = f2tf(a0 - __uint_as_float(Ah[kt][0]));
                Ah[kt][1] = f2tf(a1); Al[kt][1] = f2tf(a1 - __uint_as_float(Ah[kt][1]));
                Ah[kt][2] = f2tf(a2); Al[kt][2] = f2tf(a2 - __uint_as_float(Ah[kt][2]));
                Ah[kt][3] = f2tf(a3); Al[kt][3] = f2tf(a3 - __uint_as_float(Ah[kt][3]));
            }
            x2r0 += __shfl_xor_sync(0xFFFFFFFFu, x2r0, 1);
            x2r0 += __shfl_xor_sync(0xFFFFFFFFu, x2r0, 2);
            x2r1 += __shfl_xor_sync(0xFFFFFFFFu, x2r1, 1);
            x2r1 += __shfl_xor_sync(0xFFFFFFFFu, x2r1, 2);

            float Q[8][4];
            #pragma unroll
            for (int dt = 0; dt < 8; dt++) { Q[dt][0] = Q[dt][1] = Q[dt][2] = Q[dt][3] = 0.f; }

            float sA = 0.f, sB = 0.f;
            float d1A = -3.4e38f, d2A = -3.4e38f, d1B = -3.4e38f, d2B = -3.4e38f;
            int kA = 0, kB = 0;

            #pragma unroll 1
            for (int nt = 0; nt < NT; nt++) {
                // GEMM1: 3xTF32 dots for 8 codes (in-loop cvt; cost hidden by MMA wall)
                float c0 = 0.f, c1 = 0.f, c2 = 0.f, c3 = 0.f;
                const float* bp = wsh + (nt * 8 + g) * WST;
                #pragma unroll
                for (int kt = 0; kt < 8; kt++) {
                    float b0f = bp[kt * 8 + t], b1f = bp[kt * 8 + t + 4];
                    u32 b0h = f2tf(b0f), b1h = f2tf(b1f);
                    u32 b0l = f2tf(b0f - __uint_as_float(b0h));
                    u32 b1l = f2tf(b1f - __uint_as_float(b1h));
                    mma8(c0, c1, c2, c3, Ah[kt][0], Ah[kt][1], Ah[kt][2], Ah[kt][3], b0h, b1h);
                    mma8(c0, c1, c2, c3, Al[kt][0], Al[kt][1], Al[kt][2], Al[kt][3], b0h, b1h);
                    mma8(c0, c1, c2, c3, Ah[kt][0], Ah[kt][1], Ah[kt][2], Ah[kt][3], b0l, b1l);
                }
                int n0 = nt * 8 + 2 * t, n1 = n0 + 1;
                float w20 = w2sh[n0], w21 = w2sh[n1];
                float di0 = fast_negsqrt(fmaxf(x2r0 + w20 - 2.f * c0, 0.f));
                float di1 = fast_negsqrt(fmaxf(x2r0 + w21 - 2.f * c1, 0.f));
                float di2 = fast_negsqrt(fmaxf(x2r1 + w20 - 2.f * c2, 0.f));
                float di3 = fast_negsqrt(fmaxf(x2r1 + w21 - 2.f * c3, 0.f));
                float e0 = __expf(di0), e1 = __expf(di1), e2 = __expf(di2), e3 = __expf(di3);
                sA += e0 + e1; sB += e2 + e3;

                if (di0 > d1A) { d2A = d1A; d1A = di0; kA = n0; } else if (di0 > d2A) d2A = di0;
                if (di1 > d1A) { d2A = d1A; d1A = di1; kA = n1; } else if (di1 > d2A) d2A = di1;
                if (di2 > d1B) { d2B = d1B; d1B = di2; kB = n0; } else if (di2 > d2B) d2B = di2;
                if (di3 > d1B) { d2B = d1B; d1B = di3; kB = n1; } else if (di3 > d2B) d2B = di3;

                // P tile through SMEM: C-layout -> A-layout re-fragmentation
                __syncwarp();
                ps[g * 9 + 2 * t]           = e0;
                ps[g * 9 + 2 * t + 1]       = e1;
                ps[(g + 8) * 9 + 2 * t]     = e2;
                ps[(g + 8) * 9 + 2 * t + 1] = e3;
                __syncwarp();
                float p0f = ps[g * 9 + t],       p1f = ps[(g + 8) * 9 + t];
                float p2f = ps[g * 9 + t + 4],   p3f = ps[(g + 8) * 9 + t + 4];
                u32 p0h = f2tf(p0f), p0l = f2tf(p0f - __uint_as_float(p0h));
                u32 p1h = f2tf(p1f), p1l = f2tf(p1f - __uint_as_float(p1h));
                u32 p2h = f2tf(p2f), p2l = f2tf(p2f - __uint_as_float(p2h));
                u32 p3h = f2tf(p3f), p3l = f2tf(p3f - __uint_as_float(p3h));

                // GEMM2: Q += P @ W (2-pass exact-P x tf32-W; R14-validated 1.25e-4)
                const float* b2p = wsh + (nt * 8 + t) * WST;
                #pragma unroll
                for (int dt = 0; dt < 8; dt++) {
                    u32 b0 = f2tf(b2p[dt * 8 + g]);
                    u32 b1 = f2tf(b2p[4 * WST + dt * 8 + g]);
                    mma8(Q[dt][0], Q[dt][1], Q[dt][2], Q[dt][3], p0h, p1h, p2h, p3h, b0, b1);
                    mma8(Q[dt][0], Q[dt][1], Q[dt][2], Q[dt][3], p0l, p1l, p2l, p3l, b0, b1);
                }
            }

            // Reduce sums and top-2 across the 4-lane quad
            sA += __shfl_xor_sync(0xFFFFFFFFu, sA, 1);
            sA += __shfl_xor_sync(0xFFFFFFFFu, sA, 2);
            sB += __shfl_xor_sync(0xFFFFFFFFu, sB, 1);
            sB += __shfl_xor_sync(0xFFFFFFFFu, sB, 2);
            #pragma unroll
            for (int m = 1; m <= 2; m <<= 1) {
                float o1 = __shfl_xor_sync(0xFFFFFFFFu, d1A, m);
                float o2 = __shfl_xor_sync(0xFFFFFFFFu, d2A, m);
                int   ok = __shfl_xor_sync(0xFFFFFFFFu, kA, m);
                if (o1 > d1A) { d2A = fmaxf(d1A, o2); d1A = o1; kA = ok; }
                else          { d2A = fmaxf(d2A, o1); }
                o1 = __shfl_xor_sync(0xFFFFFFFFu, d1B, m);
                o2 = __shfl_xor_sync(0xFFFFFFFFu, d2B, m);
                ok = __shfl_xor_sync(0xFFFFFFFFu, kB, m);
                if (o1 > d1B) { d2B = fmaxf(d1B, o2); d1B = o1; kB = ok; }
                else          { d2B = fmaxf(d2B, o1); }
            }

            float invA = 1.f / sA, invB = 1.f / sB;
            if (v0) {
                #pragma unroll
                for (int dt = 0; dt < 8; dt++) {
                    float2 q; q.x = Q[dt][0] * invA; q.y = Q[dt][1] * invA;
                    *(float2*)(outq + (size_t)row0 * DD + dt * 8 + 2 * t) = q;
                }
            }
            if (v1) {
                #pragma unroll
                for (int dt = 0; dt < 8; dt++) {
                    float2 q; q.x = Q[dt][2] * invB; q.y = Q[dt][3] * invB;
                    *(float2*)(outq + (size_t)row1 * DD + dt * 8 + 2 * t) = q;
                }
            }
            if (outidx && t == 0) {
                if (v0) {
                    int b = kA;
                    if (d1A - d2A < TIE_TAU) b = cold_resolve(x + (size_t)row0 * DD, w, w2em);
                    outidx[row0] = (float)b;
                }
                if (v1) {
                    int b = kB;
                    if (d1B - d2B < TIE_TAU) b = cold_resolve(x + (size_t)row1 * DD, w, w2em);
                    outidx[row1] = (float)b;
                }
            }
        }
    }
}

// Ortho loss: mean((norm_w @ norm_w^T)^2) - 1/K
#define OSTRIDE 65
#define SMEM_ORTHO (KK * OSTRIDE * 4)

__global__ __launch_bounds__(256)
void sq_ortho(const float* __restrict__ w, float* __restrict__ loss) {
    extern __shared__ float smo[];
    for (int idx = threadIdx.x; idx < KK * DD; idx += blockDim.x) {
        int r = idx >> 6, c = idx & 63;
        smo[r * OSTRIDE + c] = w[idx];
    }
    __syncthreads();
    for (int k = threadIdx.x; k < KK; k += blockDim.x) {
        float* r = smo + k * OSTRIDE;
        float n2 = 0.f;
        #pragma unroll 16
        for (int d = 0; d < DD; d++) n2 += r[d] * r[d];
        float inv = 1.f / fmaxf(sqrtf(n2), 1e-12f);
        #pragma unroll 16
        for (int d = 0; d < DD; d++) r[d] *= inv;
    }
    __syncthreads();
    float local = 0.f;
    int total = KK * KK;
    for (int p = blockIdx.x * blockDim.x + threadIdx.x; p < total;
         p += gridDim.x * blockDim.x) {
        int i = p >> 9, j = p & (KK - 1);
        const float* ri = smo + i * OSTRIDE;
        const float* rj = smo + j * OSTRIDE;
        float c = 0.f;
        #pragma unroll 16
        for (int d = 0; d < DD; d++) c += ri[d] * rj[d];
        local += c * c;
    }
    for (int off = 16; off > 0; off >>= 1)
        local += __shfl_down_sync(0xFFFFFFFF, local, off);
    __shared__ float red[8];
    int wid = threadIdx.x >> 5, lid = threadIdx.x & 31;
    if (lid == 0) red[wid] = local;
    __syncthreads();
    if (threadIdx.x == 0) {
        float bs = 0.f;
        for (int i = 0; i < (int)(blockDim.x >> 5); i++) bs += red[i];
        atomicAdd(loss, bs * (1.f / ((float)KK * (float)KK)));
        if (blockIdx.x == 0) atomicAdd(loss, -1.f / (float)KK);
    }
}

extern "C" void kernel_launch(void* const* d_in, const int* in_sizes, int n_in,
                              void* d_out, int out_size) {
    const float* x = (const float*)d_in[0];
    const float* w = (const float*)d_in[1];
    int N = in_sizes[0] / DD;

    float* out = (float*)d_out;
    size_t qn = (size_t)N * DD;
    float* outloss = nullptr;
    float* outidx  = nullptr;
    long long os = (long long)out_size;
    if (os >= (long long)(qn + 1 + (size_t)N)) {         // [quantized | loss | indices]
        outloss = out + qn;
        outidx  = out + qn + 1;
    } else if (os == (long long)(qn + (size_t)N)) {      // [quantized | indices]
        outidx = out + qn;
    } else if (os == (long long)(qn + 1)) {              // [quantized | loss]
        outloss = out + qn;
    }

    cudaFuncSetAttribute(sq_main,  cudaFuncAttributeMaxDynamicSharedMemorySize, SMEM_MAIN);
    cudaFuncSetAttribute(sq_ortho, cudaFuncAttributeMaxDynamicSharedMemorySize, SMEM_ORTHO);

    int grid = (N + ROWS_PER_CTA - 1) / ROWS_PER_CTA;
    sq_main<<<grid, NTHREADS, SMEM_MAIN>>>(x, w, out, outidx, N);

    if (outloss) {
        cudaMemsetAsync(outloss, 0, sizeof(float));
        sq_ortho<<<128, 256, SMEM_ORTHO>>>(w, outloss);
    }
}

// round 17
// speedup vs baseline: 1.0607x; 1.0607x over previous
#include <cuda_runtime.h>
#include <math.h>
#include <stdint.h>

#define DD 64
#define KK 512
#define WSTRIDE 68          // 4 mod 32 -> conflict-free (g,t) fragment loads
#define WLSTRIDE 34         // u32 words per code for bf16-packed lo
#define ROWS_PER_CTA 192
#define NTHREADS 384
#define NWARP 12
#define NT (KK / 8)
#define TIE_TAU 3e-5f

// SMEM layout (32-bit words)
#define SM_WH   0
#define SM_WL   (KK * WSTRIDE)
#define SM_W2   (SM_WL + KK * WLSTRIDE)
#define SM_W2EM (SM_W2 + KK)
#define SM_PS   (SM_W2EM + KK)
#define SMEM_WORDS (SM_PS + NWARP * 144)
#define SMEM_MAIN (SMEM_WORDS * 4)

typedef uint32_t u32;

__device__ __forceinline__ u32 f2tf(float x) {
    u32 r; asm("cvt.rna.tf32.f32 %0,%1;" : "=r"(r) : "f"(x)); return r;
}

__device__ __forceinline__ u32 bf16pack(float lo0, float lo1) {
    u32 u0 = __float_as_uint(lo0); u0 = (u0 + 0x7fffu + ((u0 >> 16) & 1u)) >> 16;
    u32 u1 = __float_as_uint(lo1); u1 = (u1 + 0x7fffu + ((u1 >> 16) & 1u)) >> 16;
    return u0 | (u1 << 16);
}

__device__ __forceinline__ void mma8(float& c0, float& c1, float& c2, float& c3,
                                     u32 a0, u32 a1, u32 a2, u32 a3,
                                     u32 b0, u32 b1) {
    asm volatile(
        "mma.sync.aligned.m16n8k8.row.col.f32.tf32.tf32.f32 "
        "{%0,%1,%2,%3},{%4,%5,%6,%7},{%8,%9},{%0,%1,%2,%3};"
        : "+f"(c0), "+f"(c1), "+f"(c2), "+f"(c3)
        : "r"(a0), "r"(a1), "r"(a2), "r"(a3), "r"(b0), "r"(b1));
}

// Reference-style squared-norm (cold path, R6-validated).
__device__ __forceinline__ float ref_norm2(const float* __restrict__ r) {
    float a[32];
    #pragma unroll
    for (int j = 0; j < 32; j++)
        a[j] = __fadd_rn(__fmul_rn(r[j], r[j]), __fmul_rn(r[j + 32], r[j + 32]));
    #pragma unroll
    for (int j = 0; j < 16; j++) a[j] = __fadd_rn(a[j], a[j + 16]);
    #pragma unroll
    for (int j = 0; j < 8; j++)  a[j] = __fadd_rn(a[j], a[j + 8]);
    #pragma unroll
    for (int j = 0; j < 4; j++)  a[j] = __fadd_rn(a[j], a[j + 4]);
    a[0] = __fadd_rn(a[0], a[2]); a[1] = __fadd_rn(a[1], a[3]);
    return __fadd_rn(a[0], a[1]);
}

__device__ __forceinline__ float fast_negsqrt(float d2) {
    float d2c = fmaxf(d2, 1e-30f);
    return -(d2c * rsqrtf(d2c));
}

// Cold path (rare, R6-validated): bit-faithful reference emulation. GMEM inputs.
__device__ __noinline__ int cold_resolve(const float* __restrict__ xr,
                                         const float* __restrict__ wg,
                                         const float* __restrict__ w2em) {
    float xf[DD];
    #pragma unroll
    for (int d = 0; d < DD; d++) xf[d] = xr[d];
    float x2em = ref_norm2(xf);

    float distbuf[KK];
    float m = -3.4e38f;
    #pragma unroll 1
    for (int k = 0; k < KK; k++) {
        const float* r = wg + k * DD;
        float acc = 0.f;
        #pragma unroll
        for (int d = 0; d < DD; d++) acc = __fmaf_rn(xf[d], r[d], acc);
        float d2 = __fsub_rn(__fadd_rn(x2em, w2em[k]), __fmul_rn(2.f, acc));
        if (d2 < 0.f) d2 = 0.f;
        float dist = -__fsqrt_rn(d2);
        distbuf[k] = dist;
        m = fmaxf(m, dist);
    }
    float ssum = 0.f;
    #pragma unroll 1
    for (int k = 0; k < KK; k++)
        ssum = __fadd_rn(ssum, (float)exp((double)__fsub_rn(distbuf[k], m)));
    float bestv = -1.f;
    int bk = 0;
    #pragma unroll 1
    for (int k = 0; k < KK; k++) {
        float e = (float)exp((double)__fsub_rn(distbuf[k], m));
        float v = __fdiv_rn(e, ssum);
        if (v > bestv) { bestv = v; bk = k; }
    }
    return bk;
}

__global__ __launch_bounds__(NTHREADS, 1)
void sq_main(const float* __restrict__ x, const float* __restrict__ w,
             float* __restrict__ outq, float* __restrict__ outidx, int N) {
    extern __shared__ u32 smw[];
    float* Wh   = (float*)(smw + SM_WH);
    u32*   Wl   = smw + SM_WL;
    float* w2sh = (float*)(smw + SM_W2);
    float* w2em = (float*)(smw + SM_W2EM);

    int tid = threadIdx.x, wid = tid >> 5, lane = tid & 31;
    int g = lane >> 2, t = lane & 3;
    int tHalf = t >> 1;
    bool oddT = (t & 1);
    int base = blockIdx.x * ROWS_PER_CTA;

    // Stage W: tf32-hi (f32, stride 68) + bf16-lo (packed, stride 34)
    for (int i = tid; i < KK * DD / 4; i += NTHREADS) {
        float4 v = ((const float4*)w)[i];
        int k = i >> 4, c = (i & 15) * 4;
        u32 h0 = f2tf(v.x), h1 = f2tf(v.y), h2 = f2tf(v.z), h3 = f2tf(v.w);
        float* dh = Wh + k * WSTRIDE + c;
        dh[0] = __uint_as_float(h0); dh[1] = __uint_as_float(h1);
        dh[2] = __uint_as_float(h2); dh[3] = __uint_as_float(h3);
        float l0 = v.x - __uint_as_float(h0), l1 = v.y - __uint_as_float(h1);
        float l2 = v.z - __uint_as_float(h2), l3 = v.w - __uint_as_float(h3);
        Wl[k * WLSTRIDE + (c >> 1)]     = bf16pack(l0, l1);
        Wl[k * WLSTRIDE + (c >> 1) + 1] = bf16pack(l2, l3);
    }
    for (int k = tid; k < KK; k += NTHREADS) {
        const float* r = w + k * DD;
        float s = 0.f;
        float rl[DD];
        #pragma unroll
        for (int d = 0; d < DD; d++) { rl[d] = r[d]; s += rl[d] * rl[d]; }
        w2sh[k] = s;
        w2em[k] = ref_norm2(rl);
    }
    __syncthreads();

    int wrow = wid * 16;
    int row0 = base + wrow + g, row1 = row0 + 8;
    bool v0 = row0 < N, v1 = row1 < N;
    const float* xr0 = x + (size_t)(v0 ? row0 : 0) * DD;
    const float* xr1 = x + (size_t)(v1 ? row1 : 0) * DD;

    uint32_t Ah[8][4], Al[8][4];
    float x2r0 = 0.f, x2r1 = 0.f;
    #pragma unroll
    for (int kt = 0; kt < 8; kt++) {
        float a0 = v0 ? xr0[kt * 8 + t]     : 0.f;
        float a1 = v1 ? xr1[kt * 8 + t]     : 0.f;
        float a2 = v0 ? xr0[kt * 8 + t + 4] : 0.f;
        float a3 = v1 ? xr1[kt * 8 + t + 4] : 0.f;
        x2r0 = fmaf(a0, a0, fmaf(a2, a2, x2r0));
        x2r1 = fmaf(a1, a1, fmaf(a3, a3, x2r1));
        Ah[kt][0] = f2tf(a0); Al[kt][0] = f2tf(a0 - __uint_as_float(Ah[kt][0]));
        Ah[kt][1] = f2tf(a1); Al[kt][1] = f2tf(a1 - __uint_as_float(Ah[kt][1]));
        Ah[kt][2] = f2tf(a2); Al[kt][2] = f2tf(a2 - __uint_as_float(Ah[kt][2]));
        Ah[kt][3] = f2tf(a3); Al[kt][3] = f2tf(a3 - __uint_as_float(Ah[kt][3]));
    }
    x2r0 += __shfl_xor_sync(0xFFFFFFFFu, x2r0, 1);
    x2r0 += __shfl_xor_sync(0xFFFFFFFFu, x2r0, 2);
    x2r1 += __shfl_xor_sync(0xFFFFFFFFu, x2r1, 1);
    x2r1 += __shfl_xor_sync(0xFFFFFFFFu, x2r1, 2);

    float Q[8][4];
    #pragma unroll
    for (int dt = 0; dt < 8; dt++) { Q[dt][0] = Q[dt][1] = Q[dt][2] = Q[dt][3] = 0.f; }

    float sA = 0.f, sB = 0.f;
    float d1A = -3.4e38f, d2A = -3.4e38f, d1B = -3.4e38f, d2B = -3.4e38f;
    int kA = 0, kB = 0;
    float* ps = (float*)(smw + SM_PS) + wid * 144;

    #pragma unroll 1
    for (int nt = 0; nt < NT; nt++) {
        // GEMM1 with SIX independent accumulator tuples (3 passes x even/odd kt):
        // critical MMA dependency chain 24 -> 4.
        float A0[4] = {0,0,0,0}, A1[4] = {0,0,0,0};   // hi*hi even/odd
        float B0[4] = {0,0,0,0}, B1[4] = {0,0,0,0};   // lo*hi even/odd
        float C0[4] = {0,0,0,0}, C1[4] = {0,0,0,0};   // hi*lo even/odd
        const float* bp = Wh + (nt * 8 + g) * WSTRIDE;
        const u32*   lp = Wl + (nt * 8 + g) * WLSTRIDE;
        #pragma unroll
        for (int kt = 0; kt < 8; kt += 2) {
            u32 b0h = __float_as_uint(bp[kt * 8 + t]);
            u32 b1h = __float_as_uint(bp[kt * 8 + t + 4]);
            u32 lw0 = lp[4 * kt + tHalf];
            u32 lw1 = lp[4 * kt + tHalf + 2];
            u32 b0l = oddT ? (lw0 & 0xffff0000u) : (lw0 << 16);
            u32 b1l = oddT ? (lw1 & 0xffff0000u) : (lw1 << 16);
            mma8(A0[0], A0[1], A0[2], A0[3], Ah[kt][0], Ah[kt][1], Ah[kt][2], Ah[kt][3], b0h, b1h);
            mma8(B0[0], B0[1], B0[2], B0[3], Al[kt][0], Al[kt][1], Al[kt][2], Al[kt][3], b0h, b1h);
            mma8(C0[0], C0[1], C0[2], C0[3], Ah[kt][0], Ah[kt][1], Ah[kt][2], Ah[kt][3], b0l, b1l);

            int ko = kt + 1;
            u32 c0h = __float_as_uint(bp[ko * 8 + t]);
            u32 c1h = __float_as_uint(bp[ko * 8 + t + 4]);
            u32 mw0 = lp[4 * ko + tHalf];
            u32 mw1 = lp[4 * ko + tHalf + 2];
            u32 c0l = oddT ? (mw0 & 0xffff0000u) : (mw0 << 16);
            u32 c1l = oddT ? (mw1 & 0xffff0000u) : (mw1 << 16);
            mma8(A1[0], A1[1], A1[2], A1[3], Ah[ko][0], Ah[ko][1], Ah[ko][2], Ah[ko][3], c0h, c1h);
            mma8(B1[0], B1[1], B1[2], B1[3], Al[ko][0], Al[ko][1], Al[ko][2], Al[ko][3], c0h, c1h);
            mma8(C1[0], C1[1], C1[2], C1[3], Ah[ko][0], Ah[ko][1], Ah[ko][2], Ah[ko][3], c0l, c1l);
        }
        float c0 = ((A0[0] + A1[0]) + (B0[0] + B1[0])) + (C0[0] + C1[0]);
        float c1 = ((A0[1] + A1[1]) + (B0[1] + B1[1])) + (C0[1] + C1[1]);
        float c2 = ((A0[2] + A1[2]) + (B0[2] + B1[2])) + (C0[2] + C1[2]);
        float c3 = ((A0[3] + A1[3]) + (B0[3] + B1[3])) + (C0[3] + C1[3]);

        int n0 = nt * 8 + 2 * t, n1 = n0 + 1;
        float w20 = w2sh[n0], w21 = w2sh[n1];
        float di0 = fast_negsqrt(fmaxf(x2r0 + w20 - 2.f * c0, 0.f));
        float di1 = fast_negsqrt(fmaxf(x2r0 + w21 - 2.f * c1, 0.f));
        float di2 = fast_negsqrt(fmaxf(x2r1 + w20 - 2.f * c2, 0.f));
        float di3 = fast_negsqrt(fmaxf(x2r1 + w21 - 2.f * c3, 0.f));
        float e0 = __expf(di0), e1 = __expf(di1), e2 = __expf(di2), e3 = __expf(di3);
        sA += e0 + e1; sB += e2 + e3;

        if (di0 > d1A) { d2A = d1A; d1A = di0; kA = n0; } else if (di0 > d2A) d2A = di0;
        if (di1 > d1A) { d2A = d1A; d1A = di1; kA = n1; } else if (di1 > d2A) d2A = di1;
        if (di2 > d1B) { d2B = d1B; d1B = di2; kB = n0; } else if (di2 > d2B) d2B = di2;
        if (di3 > d1B) { d2B = d1B; d1B = di3; kB = n1; } else if (di3 > d2B) d2B = di3;

        // P tile through SMEM: C-layout -> A-layout re-fragmentation
        __syncwarp();
        ps[g * 9 + 2 * t]           = e0;
        ps[g * 9 + 2 * t + 1]       = e1;
        ps[(g + 8) * 9 + 2 * t]     = e2;
        ps[(g + 8) * 9 + 2 * t + 1] = e3;
        __syncwarp();
        float p0f = ps[g * 9 + t],       p1f = ps[(g + 8) * 9 + t];
        float p2f = ps[g * 9 + t + 4],   p3f = ps[(g + 8) * 9 + t + 4];
        u32 p0h = f2tf(p0f), p0l = f2tf(p0f - __uint_as_float(p0h));
        u32 p1h = f2tf(p1f), p1l = f2tf(p1f - __uint_as_float(p1h));
        u32 p2h = f2tf(p2f), p2l = f2tf(p2f - __uint_as_float(p2h));
        u32 p3h = f2tf(p3f), p3l = f2tf(p3f - __uint_as_float(p3h));

        // GEMM2: Q += P @ Wh (8 independent chains; R14-validated accuracy)
        const float* b2p = Wh + (nt * 8 + t) * WSTRIDE;
        #pragma unroll
        for (int dt = 0; dt < 8; dt++) {
            u32 b0 = __float_as_uint(b2p[dt * 8 + g]);
            u32 b1 = __float_as_uint(b2p[4 * WSTRIDE + dt * 8 + g]);
            mma8(Q[dt][0], Q[dt][1], Q[dt][2], Q[dt][3], p0h, p1h, p2h, p3h, b0, b1);
            mma8(Q[dt][0], Q[dt][1], Q[dt][2], Q[dt][3], p0l, p1l, p2l, p3l, b0, b1);
        }
    }

    // Reduce softmax sums and top-2 across the 4-lane quad
    sA += __shfl_xor_sync(0xFFFFFFFFu, sA, 1);
    sA += __shfl_xor_sync(0xFFFFFFFFu, sA, 2);
    sB += __shfl_xor_sync(0xFFFFFFFFu, sB, 1);
    sB += __shfl_xor_sync(0xFFFFFFFFu, sB, 2);
    #pragma unroll
    for (int m = 1; m <= 2; m <<= 1) {
        float o1 = __shfl_xor_sync(0xFFFFFFFFu, d1A, m);
        float o2 = __shfl_xor_sync(0xFFFFFFFFu, d2A, m);
        int   ok = __shfl_xor_sync(0xFFFFFFFFu, kA, m);
        if (o1 > d1A) { d2A = fmaxf(d1A, o2); d1A = o1; kA = ok; }
        else          { d2A = fmaxf(d2A, o1); }
        o1 = __shfl_xor_sync(0xFFFFFFFFu, d1B, m);
        o2 = __shfl_xor_sync(0xFFFFFFFFu, d2B, m);
        ok = __shfl_xor_sync(0xFFFFFFFFu, kB, m);
        if (o1 > d1B) { d2B = fmaxf(d1B, o2); d1B = o1; kB = ok; }
        else          { d2B = fmaxf(d2B, o1); }
    }

    float invA = 1.f / sA, invB = 1.f / sB;
    if (v0) {
        #pragma unroll
        for (int dt = 0; dt < 8; dt++) {
            float2 q; q.x = Q[dt][0] * invA; q.y = Q[dt][1] * invA;
            *(float2*)(outq + (size_t)row0 * DD + dt * 8 + 2 * t) = q;
        }
    }
    if (v1) {
        #pragma unroll
        for (int dt = 0; dt < 8; dt++) {
            float2 q; q.x = Q[dt][2] * invB; q.y = Q[dt][3] * invB;
            *(float2*)(outq + (size_t)row1 * DD + dt * 8 + 2 * t) = q;
        }
    }

    if (outidx && t == 0) {
        if (v0) {
            int bk = kA;
            if (d1A - d2A < TIE_TAU) bk = cold_resolve(x + (size_t)row0 * DD, w, w2em);
            outidx[row0] = (float)bk;
        }
        if (v1) {
            int bk = kB;
            if (d1B - d2B < TIE_TAU) bk = cold_resolve(x + (size_t)row1 * DD, w, w2em);
            outidx[row1] = (float)bk;
        }
    }
}

// Ortho loss: mean((norm_w @ norm_w^T)^2) - 1/K
#define OSTRIDE 65
#define SMEM_ORTHO (KK * OSTRIDE * 4)

__global__ __launch_bounds__(256)
void sq_ortho(const float* __restrict__ w, float* __restrict__ loss) {
    extern __shared__ float sm[];
    for (int idx = threadIdx.x; idx < KK * DD; idx += blockDim.x) {
        int r = idx >> 6, c = idx & 63;
        sm[r * OSTRIDE + c] = w[idx];
    }
    __syncthreads();
    for (int k = threadIdx.x; k < KK; k += blockDim.x) {
        float* r = sm + k * OSTRIDE;
        float n2 = 0.f;
        #pragma unroll 16
        for (int d = 0; d < DD; d++) n2 += r[d] * r[d];
        float inv = 1.f / fmaxf(sqrtf(n2), 1e-12f);
        #pragma unroll 16
        for (int d = 0; d < DD; d++) r[d] *= inv;
    }
    __syncthreads();

    float local = 0.f;
    int total = KK * KK;
    for (int p = blockIdx.x * blockDim.x + threadIdx.x; p < total;
         p += gridDim.x * blockDim.x) {
        int i = p >> 9, j = p & (KK - 1);
        const float* ri = sm + i * OSTRIDE;
        const float* rj = sm + j * OSTRIDE;
        float c = 0.f;
        #pragma unroll 16
        for (int d = 0; d < DD; d++) c += ri[d] * rj[d];
        local += c * c;
    }
    for (int off = 16; off > 0; off >>= 1)
        local += __shfl_down_sync(0xFFFFFFFF, local, off);
    __shared__ float red[8];
    int wid = threadIdx.x >> 5, lid = threadIdx.x & 31;
    if (lid == 0) red[wid] = local;
    __syncthreads();
    if (threadIdx.x == 0) {
        float bs = 0.f;
        for (int i = 0; i < (int)(blockDim.x >> 5); i++) bs += red[i];
        atomicAdd(loss, bs * (1.f / ((float)KK * (float)KK)));
        if (blockIdx.x == 0) atomicAdd(loss, -1.f / (float)KK);
    }
}

extern "C" void kernel_launch(void* const* d_in, const int* in_sizes, int n_in,
                              void* d_out, int out_size) {
    const float* x = (const float*)d_in[0];
    const float* w = (const float*)d_in[1];
    int N = in_sizes[0] / DD;

    float* out = (float*)d_out;
    size_t qn = (size_t)N * DD;
    float* outloss = nullptr;
    float* outidx  = nullptr;
    long long os = (long long)out_size;
    if (os >= (long long)(qn + 1 + (size_t)N)) {         // [quantized | loss | indices]
        outloss = out + qn;
        outidx  = out + qn + 1;
    } else if (os == (long long)(qn + (size_t)N)) {      // [quantized | indices]
        outidx = out + qn;
    } else if (os == (long long)(qn + 1)) {              // [quantized | loss]
        outloss = out + qn;
    }

    cudaFuncSetAttribute(sq_main,  cudaFuncAttributeMaxDynamicSharedMemorySize, SMEM_MAIN);
    cudaFuncSetAttribute(sq_ortho, cudaFuncAttributeMaxDynamicSharedMemorySize, SMEM_ORTHO);

    // sq_ortho launched FIRST (independent of sq_main) so ncu's skip-5 capture
    // lands on sq_main instead of sq_ortho.
    if (outloss) {
        cudaMemsetAsync(outloss, 0, sizeof(float));
        sq_ortho<<<128, 256, SMEM_ORTHO>>>(w, outloss);
    }

    int grid = (N + ROWS_PER_CTA - 1) / ROWS_PER_CTA;
    sq_main<<<grid, NTHREADS, SMEM_MAIN>>>(x, w, out, outidx, N);
}